// round 16
// baseline (speedup 1.0000x reference)
#include <cuda_runtime.h>
#include <cstddef>

// DilatedKNN: B=4, N=8192, C=64, K=9, d=2 -> top-18 nearest, slice ::2.
// Output float32. key = max((|s|^2+|q|^2) - 2*dot, 0).
// INVARIANT: every dot / norm = ONE sequential fmaf chain over ascending k.
// Keys bit-identical to R13 -> rel_err must be exactly 7.627561e-4.
//
// R16: duplicated-candidate packing. fma2 lanes = (dot(q_even,c), dot(q_odd,c))
// via (q_e[k],q_o[k]) x (c[k],c[k]); candidate tile stored pre-duplicated so
// one LDS.128 yields both packed operands. Kills the swapped-q stream, the
// cross-term transpose, and halves accumulator regs (R15's spill cause).

#define BATCH 4
#define NPTS  8192
#define CDIM  64
#define KOUT  9
#define KK    18
#define MQ    64      // queries per block
#define TSC   64      // candidate tile rows
#define TPB   128
#define NK2   32

// smem floats:
//  qs   : 32 k2 x 33 u2  = 4224   @ 0
//  cdup : 32 k2 x 64 u2  = 8192   @ 4224   (also merge-list alias)
//  d2s  : 64 x 67        = 4288   @ 12416
//  sS   : 64                      @ 16704
#define SM_CD     4224
#define SM_D2     12416
#define SM_SS     16704
#define SM_FLOATS 16768

__device__ float g_sq[BATCH * NPTS];

__device__ __forceinline__ void fma2(unsigned long long& d,
                                     unsigned long long a,
                                     unsigned long long b) {
    asm("fma.rn.f32x2 %0, %1, %2, %0;" : "+l"(d) : "l"(a), "l"(b));
}
__device__ __forceinline__ float2 unpack2(unsigned long long v) {
    float2 r;
    asm("mov.b64 {%0, %1}, %2;" : "=f"(r.x), "=f"(r.y) : "l"(v));
    return r;
}

// ---- norms: one thread per row, sequential ascending-k fmaf chain ----
__global__ void __launch_bounds__(256) sq_kernel(const float* __restrict__ q) {
    int r = blockIdx.x * 256 + threadIdx.x;
    if (r >= BATCH * NPTS) return;
    const float* row = q + (size_t)r * CDIM;
    float s = 0.f;
#pragma unroll
    for (int c = 0; c < CDIM; c++) s = fmaf(row[c], row[c], s);
    g_sq[r] = s;
}

__global__ void __launch_bounds__(TPB, 3)
knn_kernel(const float* __restrict__ q, float* __restrict__ out) {
    extern __shared__ float smem[];
    float4*     qs4 = (float4*)smem;
    ulonglong2* qsU = (ulonglong2*)smem;
    float4*     cd4 = (float4*)(smem + SM_CD);
    ulonglong2* cdU = (ulonglong2*)(smem + SM_CD);
    float*      d2s = smem + SM_D2;
    float*      sS  = smem + SM_SS;

    const int b  = blockIdx.x >> 7;           // 128 blocks per batch
    const int q0 = (blockIdx.x & 127) * MQ;
    const float* qb = q + (size_t)b * NPTS * CDIM;
    const int tid = threadIdx.x;
    const int tx  = tid & 15;                 // candidates tx+16*cp (cp 0..3)
    const int ty  = tid >> 4;                 // qpairs ty+8*jp     (jp 0..3)
    const int qi  = tid & 63;                 // phase-B query
    const int h   = tid >> 6;                 // phase-B half (0/1)

    // ---- query tile: pair-interleaved (qe,qo) per k ----
    for (int t = tid; t < 32 * 16; t += TPB) {
        int p = t >> 4, kc = t & 15;
        float4 a = ((const float4*)(qb + (size_t)(q0 + 2 * p) * CDIM))[kc];
        float4 c = ((const float4*)(qb + (size_t)(q0 + 2 * p + 1) * CDIM))[kc];
        qs4[(2 * kc) * 33 + p]     = make_float4(a.x, c.x, a.y, c.y);
        qs4[(2 * kc + 1) * 33 + p] = make_float4(a.z, c.z, a.w, c.w);
    }
    const float sqm = g_sq[b * NPTS + q0 + qi];

    float kd[KK];
    int   ki[KK];
#pragma unroll
    for (int j = 0; j < KK; j++) { kd[j] = 3.402823466e38f; ki[j] = 0; }

    for (int c0 = 0; c0 < NPTS; c0 += TSC) {
        __syncthreads();   // qs ready (1st iter) / prev phase A done with cdup
        // ---- candidate tile, value-duplicated: (c[k],c[k],c[k+1],c[k+1]) ----
        for (int t = tid; t < TSC * 16; t += TPB) {
            int r = t >> 4, kc = t & 15;
            float4 v = ((const float4*)(qb + (size_t)(c0 + r) * CDIM))[kc];
            cd4[(2 * kc) * 64 + r]     = make_float4(v.x, v.x, v.y, v.y);
            cd4[(2 * kc + 1) * 64 + r] = make_float4(v.z, v.z, v.w, v.w);
        }
        if (tid < TSC) sS[tid] = g_sq[b * NPTS + c0 + tid];
        __syncthreads();   // tile + norms visible

        // ---- phase A: (8 q-rows) x (4 candidates) packed dots ----
        unsigned long long acc[4][4];
#pragma unroll
        for (int jp = 0; jp < 4; jp++)
#pragma unroll
            for (int cp = 0; cp < 4; cp++) acc[jp][cp] = 0ull;

#pragma unroll 8
        for (int k2 = 0; k2 < NK2; k2++) {
            ulonglong2 qa[4], cv[4];
#pragma unroll
            for (int jp = 0; jp < 4; jp++) qa[jp] = qsU[k2 * 33 + ty + 8 * jp];
#pragma unroll
            for (int cp = 0; cp < 4; cp++) cv[cp] = cdU[k2 * 64 + tx + 16 * cp];
#pragma unroll
            for (int jp = 0; jp < 4; jp++)
#pragma unroll
                for (int cp = 0; cp < 4; cp++) {
                    fma2(acc[jp][cp], qa[jp].x, cv[cp].x);  // k   : (qe*c, qo*c)
                    fma2(acc[jp][cp], qa[jp].y, cv[cp].y);  // k+1
                }
        }

        // ---- store dots: lane0 -> even q-row, lane1 -> odd q-row ----
#pragma unroll
        for (int jp = 0; jp < 4; jp++)
#pragma unroll
            for (int cp = 0; cp < 4; cp++) {
                float2 f = unpack2(acc[jp][cp]);
                int qe = 2 * (ty + 8 * jp);
                int c  = tx + 16 * cp;
                d2s[qe * 67 + c]       = f.x;
                d2s[(qe + 1) * 67 + c] = f.y;
            }
        __syncthreads();   // dots visible

        // ---- phase B: my half-row (32 candidates) ----
        const float* row = d2s + qi * 67 + h * 32;
        const float* ns  = sS + h * 32;
        const int base = c0 + h * 32;
#pragma unroll 4
        for (int s = 0; s < 32; s++) {
            float t   = ns[s] + sqm;
            float d2  = t - 2.0f * row[s];
            float key = fmaxf(d2, 0.0f);
            if (key < kd[KK - 1]) {
                kd[KK - 1] = key;
                ki[KK - 1] = base + s;
#pragma unroll
                for (int j = KK - 1; j >= 1; --j) {
                    if (kd[j] < kd[j - 1]) {
                        float tk = kd[j]; kd[j] = kd[j - 1]; kd[j - 1] = tk;
                        int   ti = ki[j]; ki[j] = ki[j - 1]; ki[j - 1] = ti;
                    }
                }
            }
        }
    }

    // ---- merge two half-lists per query (stable by (key, idx)) ----
    __syncthreads();                         // last phase B done
    float* mk = smem + SM_CD;                // 128 slots x 18 keys (cdup alias)
    int*   mi = (int*)(smem + SM_CD + 2304); // 128 slots x 18 idx
    {
        int slot = qi * 2 + h;
#pragma unroll
        for (int j = 0; j < KK; j++) {
            mk[slot * KK + j] = kd[j];
            mi[slot * KK + j] = ki[j];
        }
    }
    __syncthreads();
    if (tid < MQ) {
        const float* ka = mk + (tid * 2) * KK;
        const int*   ia = mi + (tid * 2) * KK;
        const float* kb = ka + KK;
        const int*   ib = ia + KK;
        float* orow = out + ((size_t)(b * NPTS + q0 + tid)) * KOUT;
        int pa = 0, pb = 0;
#pragma unroll
        for (int j = 0; j < KK; j++) {
            float k0 = ka[pa], k1 = kb[pb];
            int   i0 = ia[pa], i1 = ib[pb];
            bool takeA = (k0 < k1) || (k0 == k1 && i0 < i1);
            int sel = takeA ? i0 : i1;
            if ((j & 1) == 0) orow[j >> 1] = (float)sel;   // dilated ::2
            pa += takeA ? 1 : 0;
            pb += takeA ? 0 : 1;
        }
    }
}

// ---------------------------------------------------------------------------
extern "C" void kernel_launch(void* const* d_in, const int* in_sizes, int n_in,
                              void* d_out, int out_size) {
    const float* q = (const float*)d_in[0];
    float* out = (float*)d_out;
    size_t smem_bytes = (size_t)SM_FLOATS * sizeof(float);   // ~65.5 KB
    cudaFuncSetAttribute(knn_kernel,
                         cudaFuncAttributeMaxDynamicSharedMemorySize,
                         (int)smem_bytes);
    sq_kernel<<<(BATCH * NPTS + 255) / 256, 256>>>(q);
    knn_kernel<<<BATCH * (NPTS / MQ), TPB, smem_bytes>>>(q, out);
}

// round 17
// speedup vs baseline: 1.3209x; 1.3209x over previous
#include <cuda_runtime.h>
#include <cstddef>

// DilatedKNN: B=4, N=8192, C=64, K=9, d=2 -> top-18 nearest, slice ::2.
// Output float32. key = max((|s|^2+|q|^2) - 2*dot, 0).
// INVARIANT: dot/norm = ONE sequential fmaf/fma2 chain over ascending k.
// Keys bit-identical to R11/R13 -> rel_err must be exactly 7.627561e-4.
//
// R17 = R11 (best: 1657us) + (1) packed f32x2 phase-B filter with scalar
// rare-path (bit-identical insertions), (2) norms precomputed in sq_kernel,
// (3) k2 unroll 8 + launch_bounds(128,3) for 3 CTAs/SM.

#define BATCH 4
#define NPTS  8192
#define CDIM  64
#define KOUT  9
#define KK    18
#define MQ    128     // queries per block (1 query per thread, no merge)
#define TSC   64      // candidate tile rows
#define TPB   128
#define NK2   32

// smem floats:
//  qs : 32 k2 x 65 u2 = 8320 @ 0
//  U  : 8448 @ 8320:  ssm 32x33 u2 (4224) + ssw (4224)   [phase A]
//                     d2s 128 x 66 (8448)                [phase B]
//  sS : 64 @ 16768
#define SM_SSW    (8320 + 4224)
#define SM_U      8320
#define SM_SS     16768
#define SM_FLOATS 16832

__device__ float g_sq[BATCH * NPTS];

typedef unsigned long long ull;

__device__ __forceinline__ void fma2(ull& d, ull a, ull b) {
    asm("fma.rn.f32x2 %0, %1, %2, %0;" : "+l"(d) : "l"(a), "l"(b));
}
__device__ __forceinline__ ull add2(ull a, ull b) {
    ull r;
    asm("add.rn.f32x2 %0, %1, %2;" : "=l"(r) : "l"(a), "l"(b));
    return r;
}
__device__ __forceinline__ ull fma2v(ull a, ull b, ull c) {
    ull r;
    asm("fma.rn.f32x2 %0, %1, %2, %3;" : "=l"(r) : "l"(a), "l"(b), "l"(c));
    return r;
}
__device__ __forceinline__ float2 unpack2(ull v) {
    float2 r;
    asm("mov.b64 {%0, %1}, %2;" : "=f"(r.x), "=f"(r.y) : "l"(v));
    return r;
}
__device__ __forceinline__ ull pack2(float lo, float hi) {
    ull r;
    asm("mov.b64 %0, {%1, %2};" : "=l"(r) : "f"(lo), "f"(hi));
    return r;
}

// ---- norms: one thread per row, sequential ascending-k fmaf chain ----
__global__ void __launch_bounds__(256) sq_kernel(const float* __restrict__ q) {
    int r = blockIdx.x * 256 + threadIdx.x;
    if (r >= BATCH * NPTS) return;
    const float* row = q + (size_t)r * CDIM;
    float s = 0.f;
#pragma unroll
    for (int c = 0; c < CDIM; c++) s = fmaf(row[c], row[c], s);
    g_sq[r] = s;
}

__global__ void __launch_bounds__(TPB, 3)
knn_kernel(const float* __restrict__ q, float* __restrict__ out) {
    extern __shared__ float smem[];
    float4*     qs4 = (float4*)smem;
    ulonglong2* qsU = (ulonglong2*)smem;
    float4*     ss4 = (float4*)(smem + SM_U);
    ulonglong2* ssU = (ulonglong2*)(smem + SM_U);
    float4*     sw4 = (float4*)(smem + SM_SSW);
    ulonglong2* swU = (ulonglong2*)(smem + SM_SSW);
    float*      d2s = smem + SM_U;             // aliases ssm/ssw (phase B)
    float*      sS  = smem + SM_SS;

    const int b  = blockIdx.x >> 6;            // 64 blocks per batch
    const int q0 = (blockIdx.x & 63) * MQ;
    const float* qb = q + (size_t)b * NPTS * CDIM;
    const int tid = threadIdx.x;
    const int ty  = tid >> 3;                  // qpairs ty+16*jp (jp 0..3)
    const int tx  = tid & 7;                   // cpairs tx+8*cp  (cp 0..3)

    // ---- query tile: pair-interleaved (qe,qo) per k ----
    for (int t = tid; t < 64 * 16; t += TPB) {
        int p = t >> 4, kc = t & 15;
        float4 a = ((const float4*)(qb + (size_t)(q0 + 2 * p) * CDIM))[kc];
        float4 c = ((const float4*)(qb + (size_t)(q0 + 2 * p + 1) * CDIM))[kc];
        qs4[(2 * kc) * 65 + p]     = make_float4(a.x, c.x, a.y, c.y);
        qs4[(2 * kc + 1) * 65 + p] = make_float4(a.z, c.z, a.w, c.w);
    }
    const float sqm  = g_sq[b * NPTS + q0 + tid];
    const ull   sqm2 = pack2(sqm, sqm);
    const ull   m2   = pack2(-2.0f, -2.0f);

    float kd[KK];
    int   ki[KK];
#pragma unroll
    for (int j = 0; j < KK; j++) { kd[j] = 3.402823466e38f; ki[j] = 0; }

    for (int c0 = 0; c0 < NPTS; c0 += TSC) {
        __syncthreads();   // qs ready (1st) / prev d2s consumed
        // ---- candidate tile + swapped copy, pair-interleaved ----
        for (int t = tid; t < 32 * 16; t += TPB) {
            int p = t >> 4, kc = t & 15;
            float4 a = ((const float4*)(qb + (size_t)(c0 + 2 * p) * CDIM))[kc];
            float4 c = ((const float4*)(qb + (size_t)(c0 + 2 * p + 1) * CDIM))[kc];
            ss4[(2 * kc) * 33 + p]     = make_float4(a.x, c.x, a.y, c.y);
            ss4[(2 * kc + 1) * 33 + p] = make_float4(a.z, c.z, a.w, c.w);
            sw4[(2 * kc) * 33 + p]     = make_float4(c.x, a.x, c.y, a.y);
            sw4[(2 * kc + 1) * 33 + p] = make_float4(c.z, a.z, c.w, a.w);
        }
        if (tid < TSC) sS[tid] = g_sq[b * NPTS + c0 + tid];
        __syncthreads();   // tile + norms visible

        // ---- phase A: 8q x 8c packed dots (R11 layout) ----
        ull accA[4][4], accB[4][4];
#pragma unroll
        for (int jp = 0; jp < 4; jp++)
#pragma unroll
            for (int cp = 0; cp < 4; cp++) { accA[jp][cp] = 0ull; accB[jp][cp] = 0ull; }

#pragma unroll 8
        for (int k2 = 0; k2 < NK2; k2++) {
            ulonglong2 qv[4], sv[4], wv[4];
#pragma unroll
            for (int jp = 0; jp < 4; jp++) qv[jp] = qsU[k2 * 65 + ty + 16 * jp];
#pragma unroll
            for (int cp = 0; cp < 4; cp++) {
                sv[cp] = ssU[k2 * 33 + tx + 8 * cp];
                wv[cp] = swU[k2 * 33 + tx + 8 * cp];
            }
#pragma unroll
            for (int jp = 0; jp < 4; jp++)
#pragma unroll
                for (int cp = 0; cp < 4; cp++) {
                    fma2(accA[jp][cp], qv[jp].x, sv[cp].x);  // (qe*se, qo*so) k
                    fma2(accA[jp][cp], qv[jp].y, sv[cp].y);  //               k+1
                    fma2(accB[jp][cp], qv[jp].x, wv[cp].x);  // (qe*so, qo*se) k
                    fma2(accB[jp][cp], qv[jp].y, wv[cp].y);  //               k+1
                }
        }
        __syncthreads();   // phase-A reads done -> region becomes d2s

        // ---- transpose dots into d2s[q*66 + c] (all rows 8B-aligned) ----
#pragma unroll
        for (int jp = 0; jp < 4; jp++)
#pragma unroll
            for (int cp = 0; cp < 4; cp++) {
                float2 A  = unpack2(accA[jp][cp]);  // (qe.se, qo.so)
                float2 Bv = unpack2(accB[jp][cp]);  // (qe.so, qo.se)
                int qe = 2 * (ty + 16 * jp);
                int ce = 2 * (tx + 8 * cp);
                *(float2*)(d2s + qe * 66 + ce)       = make_float2(A.x, Bv.x);
                *(float2*)(d2s + (qe + 1) * 66 + ce) = make_float2(Bv.y, A.y);
            }
        __syncthreads();   // dots visible

        // ---- phase B: packed filter over my 64 candidates ----
        const float* row = d2s + tid * 66;
#pragma unroll 4
        for (int s2 = 0; s2 < TSC / 2; s2++) {
            ull rp = *(const ull*)(row + 2 * s2);      // (row[s], row[s+1])
            ull np = *(const ull*)(sS + 2 * s2);       // (sS[s], sS[s+1])
            ull tp = add2(np, sqm2);                   // sS + sqm   (lanewise)
            float2 d2p = unpack2(fma2v(rp, m2, tp));   // t - 2*row  (lanewise FFMA)
            if (fminf(d2p.x, d2p.y) < kd[KK - 1]) {    // rare path
#pragma unroll
                for (int e = 0; e < 2; e++) {
                    float key = fmaxf(e ? d2p.y : d2p.x, 0.0f);
                    if (key < kd[KK - 1]) {
                        kd[KK - 1] = key;
                        ki[KK - 1] = c0 + 2 * s2 + e;
#pragma unroll
                        for (int j = KK - 1; j >= 1; --j) {
                            if (kd[j] < kd[j - 1]) {
                                float tk = kd[j]; kd[j] = kd[j - 1]; kd[j - 1] = tk;
                                int   ti = ki[j]; ki[j] = ki[j - 1]; ki[j - 1] = ti;
                            }
                        }
                    }
                }
            }
        }
    }

    // ---- dilated slice ::2 of sorted top-18 ----
    float* orow = out + ((size_t)(b * NPTS + q0 + tid)) * KOUT;
#pragma unroll
    for (int j = 0; j < KOUT; j++) orow[j] = (float)ki[2 * j];
}

// ---------------------------------------------------------------------------
extern "C" void kernel_launch(void* const* d_in, const int* in_sizes, int n_in,
                              void* d_out, int out_size) {
    const float* q = (const float*)d_in[0];
    float* out = (float*)d_out;
    size_t smem_bytes = (size_t)SM_FLOATS * sizeof(float);   // ~65.8 KB
    cudaFuncSetAttribute(knn_kernel,
                         cudaFuncAttributeMaxDynamicSharedMemorySize,
                         (int)smem_bytes);
    sq_kernel<<<(BATCH * NPTS + 255) / 256, 256>>>(q);
    knn_kernel<<<BATCH * (NPTS / MQ), TPB, smem_bytes>>>(q, out);
}